// round 6
// baseline (speedup 1.0000x reference)
#include <cuda_runtime.h>
#include <math.h>

#define TT   500
#define BB   8
#define CC   512
#define RR   4000         // T*B rows
#define TBC  2048000      // T*B*C elements
#define LANES 4096        // B*C lanes for LIF

// ---------------- scratch (static device globals; no allocation) ----------------
__device__ float d_pre[3 * TBC];    // GEMM outputs (q,k,v) / reused for mattn & proj
__device__ float d_spk[3 * TBC];    // q,k,v spikes; later y0 (slot0) and y1 (slot1)
__device__ float d_pre2[3 * TBC];   // g_pre, l_pre, dw_pre
__device__ float d_spk2[3 * TBC];   // g,l,dw spikes
__device__ float d_dwout[TBC];      // pointwise-over-heads output
__device__ float d_M[64 * 64 * 64]; // per-(b,h) K^T V  (64 matrices of 64x64)
__device__ float d_meanb[1536];
__device__ float d_rstdb[1536];

// ---------------- SGEMM NT: C[m,n] = sum_k A[m,k] * B[n,k] ----------------
// A: [M,K] row-major, B: [N,K] row-major. BM=BN=128, BK=8, 256 threads, 8x8 microtile.
__global__ __launch_bounds__(256, 2)
void sgemm_nt(const float* __restrict__ A, const float* __restrict__ B,
              float* __restrict__ C, int M, int N, int K)
{
    __shared__ float As[8][128];
    __shared__ float Bs[8][128];
    const int bm = blockIdx.y * 128;
    const int bn = blockIdx.x * 128;
    const int tid = threadIdx.x;
    const int ty = (tid / 16) * 8;
    const int tx = (tid % 16) * 8;
    float acc[8][8];
#pragma unroll
    for (int i = 0; i < 8; i++)
#pragma unroll
        for (int j = 0; j < 8; j++) acc[i][j] = 0.f;

    const int lr = tid >> 1;        // 0..127
    const int lc = (tid & 1) * 4;   // 0 or 4
    for (int k0 = 0; k0 < K; k0 += 8) {
        float4 av = make_float4(0.f, 0.f, 0.f, 0.f);
        int arow = bm + lr;
        if (arow < M) av = *reinterpret_cast<const float4*>(A + (size_t)arow * K + k0 + lc);
        As[lc + 0][lr] = av.x; As[lc + 1][lr] = av.y; As[lc + 2][lr] = av.z; As[lc + 3][lr] = av.w;
        float4 bv = *reinterpret_cast<const float4*>(B + (size_t)(bn + lr) * K + k0 + lc);
        Bs[lc + 0][lr] = bv.x; Bs[lc + 1][lr] = bv.y; Bs[lc + 2][lr] = bv.z; Bs[lc + 3][lr] = bv.w;
        __syncthreads();
#pragma unroll
        for (int kk = 0; kk < 8; kk++) {
            float4 a0 = *reinterpret_cast<const float4*>(&As[kk][ty]);
            float4 a1 = *reinterpret_cast<const float4*>(&As[kk][ty + 4]);
            float4 b0 = *reinterpret_cast<const float4*>(&Bs[kk][tx]);
            float4 b1 = *reinterpret_cast<const float4*>(&Bs[kk][tx + 4]);
            float ar[8] = {a0.x, a0.y, a0.z, a0.w, a1.x, a1.y, a1.z, a1.w};
            float br[8] = {b0.x, b0.y, b0.z, b0.w, b1.x, b1.y, b1.z, b1.w};
#pragma unroll
            for (int i = 0; i < 8; i++)
#pragma unroll
                for (int j = 0; j < 8; j++) acc[i][j] = fmaf(ar[i], br[j], acc[i][j]);
        }
        __syncthreads();
    }
#pragma unroll
    for (int i = 0; i < 8; i++) {
        int row = bm + ty + i;
        if (row < M) {
#pragma unroll
            for (int j = 0; j < 8; j += 4) {
                float4 v = make_float4(acc[i][j], acc[i][j + 1], acc[i][j + 2], acc[i][j + 3]);
                *reinterpret_cast<float4*>(C + (size_t)row * N + bn + tx + j) = v;
            }
        }
    }
}

// ---------------- BN stats (training-mode, over T*B per channel) ----------------
__global__ void bn_stats(const float* __restrict__ pre, float* __restrict__ mean_out,
                         float* __restrict__ rstd_out)
{
    int cl = threadIdx.x & 31;
    int c  = blockIdx.x * 32 + cl;
    int rg = threadIdx.x >> 5;  // 0..7
    float s = 0.f, s2 = 0.f;
    for (int r = rg; r < RR; r += 8) {
        float v = pre[(size_t)r * CC + c];
        s += v; s2 = fmaf(v, v, s2);
    }
    __shared__ float sh1[8][32], sh2[8][32];
    sh1[rg][cl] = s; sh2[rg][cl] = s2;
    __syncthreads();
    if (rg == 0) {
#pragma unroll
        for (int i = 1; i < 8; i++) { s += sh1[i][cl]; s2 += sh2[i][cl]; }
        float m = s * (1.f / RR);
        float var = s2 * (1.f / RR) - m * m;
        mean_out[c] = m;
        rstd_out[c] = 1.f / sqrtf(var + 1e-5f);
    }
}

// ---------------- LIF scan (sequential over T, 4096*nmat lanes) ----------------
// MODE 0: plain  MODE 1: BN affine first  MODE 2: x = pre + a1 + a2
template <int MODE>
__global__ void lif_k(const float* __restrict__ pre,
                      const float* __restrict__ a1, const float* __restrict__ a2,
                      const float* __restrict__ mean, const float* __restrict__ rstd,
                      const float* __restrict__ gamma, const float* __restrict__ beta,
                      float* __restrict__ out, int nlanes)
{
    int lane = blockIdx.x * blockDim.x + threadIdx.x;
    if (lane >= nlanes) return;
    int m   = lane >> 12;
    int l12 = lane & 4095;
    const float* p = pre + (size_t)m * TBC + l12;
    float* o = out + (size_t)m * TBC + l12;
    float mn = 0.f, rs = 1.f, ga = 1.f, be = 0.f;
    if (MODE == 1) {
        int c = (m << 9) | (l12 & 511);
        mn = mean[c]; rs = rstd[c]; ga = gamma[c]; be = beta[c];
    }
    float v = 0.f;
#pragma unroll 10
    for (int t = 0; t < TT; t++) {
        float x = p[(size_t)t * LANES];
        if (MODE == 2) x = x + a1[l12 + (size_t)t * LANES] + a2[l12 + (size_t)t * LANES];
        if (MODE == 1) x = ((x - mn) * rs) * ga + be;
        float h = fmaf(v, 0.5f, x);         // v - v/2 + x  (v/2 exact)
        bool sp = (h - 1.0f) >= 0.0f;       // spike(h - VTH)
        o[(size_t)t * LANES] = sp ? 1.0f : 0.0f;
        v = sp ? 0.0f : h;                  // hard reset
    }
}

// ---------------- zero ----------------
__global__ void zero_k(float* p, int n)
{
    int i = blockIdx.x * 256 + threadIdx.x;
    if (i < n) p[i] = 0.f;
}

// ---------------- K^T V per (b,h): M[d1,d2] = sum_t k[t,d1]*v[t,d2] ----------------
__global__ void kv_outer(const float* __restrict__ kspk, const float* __restrict__ vspk,
                         float* __restrict__ M)
{
    int bh = blockIdx.x; int b = bh >> 3, h = bh & 7;
    int t0 = blockIdx.y * 100;
    __shared__ float ks[20][64], vs[20][64];
    float acc[4][4] = {};
    int ty = (threadIdx.x >> 4) << 2, tx = (threadIdx.x & 15) << 2;
    for (int tb = t0; tb < t0 + 100; tb += 20) {
        __syncthreads();
        for (int i = threadIdx.x; i < 20 * 64; i += 256) {
            int tt = i >> 6, d = i & 63, t = tb + tt;
            size_t idx = (size_t)(t * BB + b) * CC + h * 64 + d;
            ks[tt][d] = kspk[idx]; vs[tt][d] = vspk[idx];
        }
        __syncthreads();
#pragma unroll
        for (int tt = 0; tt < 20; tt++) {
            float kr[4], vr[4];
#pragma unroll
            for (int i = 0; i < 4; i++) kr[i] = ks[tt][ty + i];
#pragma unroll
            for (int j = 0; j < 4; j++) vr[j] = vs[tt][tx + j];
#pragma unroll
            for (int i = 0; i < 4; i++)
#pragma unroll
                for (int j = 0; j < 4; j++) acc[i][j] = fmaf(kr[i], vr[j], acc[i][j]);
        }
    }
    float* Mb = M + bh * 4096;
#pragma unroll
    for (int i = 0; i < 4; i++)
#pragma unroll
        for (int j = 0; j < 4; j++) atomicAdd(&Mb[(ty + i) * 64 + tx + j], acc[i][j]);
}

// ---------------- global branch: g_pre = (Q M) * gscale ----------------
__global__ void qM_k(const float* __restrict__ qspk, const float* __restrict__ M,
                     float* __restrict__ gpre, float gscale)
{
    int bh = blockIdx.x; int b = bh >> 3, h = bh & 7;
    __shared__ float Ms[64][65];
    for (int i = threadIdx.x; i < 4096; i += 256) Ms[i >> 6][i & 63] = M[bh * 4096 + i];
    __syncthreads();
    int warp = threadIdx.x >> 5, lane = threadIdx.x & 31;
    int tstart = blockIdx.y * 100;
    for (int t = tstart + warp; t < tstart + 100; t += 8) {
        size_t base = (size_t)(t * BB + b) * CC + h * 64;
        float q0 = qspk[base + lane], q1 = qspk[base + 32 + lane];
        float a0 = 0.f, a1 = 0.f;
#pragma unroll
        for (int d1 = 0; d1 < 32; d1++) {
            float qv = __shfl_sync(0xffffffffu, q0, d1);
            a0 = fmaf(qv, Ms[d1][lane], a0);
            a1 = fmaf(qv, Ms[d1][lane + 32], a1);
        }
#pragma unroll
        for (int d1 = 0; d1 < 32; d1++) {
            float qv = __shfl_sync(0xffffffffu, q1, d1);
            a0 = fmaf(qv, Ms[d1 + 32][lane], a0);
            a1 = fmaf(qv, Ms[d1 + 32][lane + 32], a1);
        }
        gpre[base + lane] = a0 * gscale;
        gpre[base + 32 + lane] = a1 * gscale;
    }
}

// ---------------- local banded attention (bit-packed popcount) ----------------
__global__ void local_k(const float* __restrict__ qspk, const float* __restrict__ kspk,
                        const float* __restrict__ vspk, float* __restrict__ lpre, float lscale)
{
    int bh = blockIdx.x; int b = bh >> 3, h = bh & 7;
    int t0 = blockIdx.y * 64;
    __shared__ unsigned long long qb[64], kb[104];
    __shared__ float vsm[104][64];
    __shared__ float ss[64][41];
    int warp = threadIdx.x >> 5, lane = threadIdx.x & 31;
    for (int r = warp; r < 64; r += 8) {
        int t = t0 + r; float v0 = 0.f, v1 = 0.f;
        if (t < TT) { size_t idx = (size_t)(t * BB + b) * CC + h * 64; v0 = qspk[idx + lane]; v1 = qspk[idx + 32 + lane]; }
        unsigned m0 = __ballot_sync(0xffffffffu, v0 > 0.5f);
        unsigned m1 = __ballot_sync(0xffffffffu, v1 > 0.5f);
        if (lane == 0) qb[r] = (unsigned long long)m0 | ((unsigned long long)m1 << 32);
    }
    for (int r = warp; r < 104; r += 8) {
        int t = t0 + r - 20; float k0 = 0.f, k1 = 0.f, w0 = 0.f, w1 = 0.f;
        if (t >= 0 && t < TT) {
            size_t idx = (size_t)(t * BB + b) * CC + h * 64;
            k0 = kspk[idx + lane]; k1 = kspk[idx + 32 + lane];
            w0 = vspk[idx + lane]; w1 = vspk[idx + 32 + lane];
        }
        unsigned m0 = __ballot_sync(0xffffffffu, k0 > 0.5f);
        unsigned m1 = __ballot_sync(0xffffffffu, k1 > 0.5f);
        if (lane == 0) kb[r] = (unsigned long long)m0 | ((unsigned long long)m1 << 32);
        vsm[r][lane] = w0; vsm[r][lane + 32] = w1;
    }
    __syncthreads();
    for (int i = threadIdx.x; i < 64 * 41; i += 256) {
        int tt = i / 41, o = i % 41;
        ss[tt][o] = (float)__popcll(qb[tt] & kb[tt + o]);
    }
    __syncthreads();
    int d = threadIdx.x & 63, tg = threadIdx.x >> 6;
    for (int tt = tg; tt < 64; tt += 4) {
        int t = t0 + tt;
        if (t >= TT) continue;
        float acc = 0.f;
#pragma unroll
        for (int o = 0; o < 41; o++) acc = fmaf(ss[tt][o], vsm[tt + o][d], acc);
        lpre[(size_t)(t * BB + b) * CC + h * 64 + d] = acc * lscale;
    }
}

// ---------------- depthwise temporal conv (9 taps along T) ----------------
__global__ void dwconv_k(const float* __restrict__ vspk, const float* __restrict__ wdw,
                         float* __restrict__ out)
{
    int i = blockIdx.x * 256 + threadIdx.x;
    if (i >= TBC) return;
    int t = i >> 12; int bc = i & 4095; int c = bc & 511; int h = c >> 6;
    float acc = 0.f;
#pragma unroll
    for (int j = 0; j < 9; j++) {
        int tt = t + j - 4;
        if (tt >= 0 && tt < TT) acc = fmaf(vspk[(size_t)tt * LANES + bc], wdw[h * 9 + j], acc);
    }
    out[i] = acc;
}

// ---------------- pointwise over heads: out[g] = sum_h spk[h] * wpw[g,h] ----------------
__global__ void pw_k(const float* __restrict__ dwspk, const float* __restrict__ wpw,
                     float* __restrict__ out)
{
    int i = blockIdx.x * 256 + threadIdx.x;  // over T*B*D = 256000
    if (i >= 256000) return;
    int t = i / 512; int bd = i % 512; int b = bd >> 6; int d = bd & 63;
    size_t base = (size_t)t * LANES + b * 512 + d;
    float s[8];
#pragma unroll
    for (int h2 = 0; h2 < 8; h2++) s[h2] = dwspk[base + h2 * 64];
#pragma unroll
    for (int g = 0; g < 8; g++) {
        float acc = 0.f;
#pragma unroll
        for (int h2 = 0; h2 < 8; h2++) acc = fmaf(s[h2], wpw[g * 8 + h2], acc);
        out[base + g * 64] = acc;
    }
}

// ---------------- host launch ----------------
extern "C" void kernel_launch(void* const* d_in, const int* in_sizes, int n_in,
                              void* d_out, int out_size)
{
    const float* x      = (const float*)d_in[0];
    const float* wq     = (const float*)d_in[1];
    const float* wk     = (const float*)d_in[2];
    const float* wv     = (const float*)d_in[3];
    const float* wmattn = (const float*)d_in[4];
    const float* wproj  = (const float*)d_in[5];
    const float* wdw    = (const float*)d_in[6];
    const float* wpw    = (const float*)d_in[7];
    const float* gamma  = (const float*)d_in[8];
    const float* beta   = (const float*)d_in[9];
    float* out = (float*)d_out;

    float *pre, *spk, *pre2, *spk2, *dwout, *M, *meanb, *rstdb;
    cudaGetSymbolAddress((void**)&pre,   d_pre);
    cudaGetSymbolAddress((void**)&spk,   d_spk);
    cudaGetSymbolAddress((void**)&pre2,  d_pre2);
    cudaGetSymbolAddress((void**)&spk2,  d_spk2);
    cudaGetSymbolAddress((void**)&dwout, d_dwout);
    cudaGetSymbolAddress((void**)&M,     d_M);
    cudaGetSymbolAddress((void**)&meanb, d_meanb);
    cudaGetSymbolAddress((void**)&rstdb, d_rstdb);

    // scales, rounded the way the numpy/python reference rounds them
    float ls32 = (float)sqrt(2624.0);          // sqrt(D*(2W+1))
    float lscale = (float)(1.0 / (double)ls32);
    float gs32 = (float)sqrt(32000.0);         // sqrt(D*(1000//2))
    float gscale = (float)(1.0 / (double)gs32);

    dim3 gemm_grid(4, 32);  // N/128 = 4, ceil(4000/128) = 32

    // spiking QKV: GEMM + BN + LIF
    sgemm_nt<<<gemm_grid, 256>>>(x, wq, pre,           RR, CC, CC);
    sgemm_nt<<<gemm_grid, 256>>>(x, wk, pre + TBC,     RR, CC, CC);
    sgemm_nt<<<gemm_grid, 256>>>(x, wv, pre + 2 * TBC, RR, CC, CC);
    bn_stats<<<16, 256>>>(pre,           meanb,        rstdb);
    bn_stats<<<16, 256>>>(pre + TBC,     meanb + 512,  rstdb + 512);
    bn_stats<<<16, 256>>>(pre + 2 * TBC, meanb + 1024, rstdb + 1024);
    lif_k<1><<<48, 256>>>(pre, nullptr, nullptr, meanb, rstdb, gamma, beta, spk, 3 * LANES);

    // global linear attention: M = K^T V, then Q M
    zero_k<<<1024, 256>>>(M, 64 * 4096);
    kv_outer<<<dim3(64, 5), 256>>>(spk + TBC, spk + 2 * TBC, M);
    qM_k<<<dim3(64, 5), 256>>>(spk, M, pre2, gscale);

    // local banded attention
    local_k<<<dim3(64, 8), 256>>>(spk, spk + TBC, spk + 2 * TBC, pre2 + TBC, lscale);

    // depthwise temporal conv on V
    dwconv_k<<<8000, 256>>>(spk + 2 * TBC, wdw, pre2 + 2 * TBC);

    // LIF over [g_pre, l_pre, dw_pre]
    lif_k<0><<<48, 256>>>(pre2, nullptr, nullptr, nullptr, nullptr, nullptr, nullptr,
                          spk2, 3 * LANES);

    // pointwise over heads on dw spikes
    pw_k<<<1000, 256>>>(spk2 + 2 * TBC, wpw, dwout);

    // y0 = LIF(g_spk + l_spk + dw_out)  -> reuse spk slot 0
    lif_k<2><<<16, 256>>>(spk2, spk2 + TBC, dwout, nullptr, nullptr, nullptr, nullptr,
                          spk, LANES);

    // mattn: GEMM + BN + LIF -> y1 (spk slot 1)
    sgemm_nt<<<gemm_grid, 256>>>(spk, wmattn, pre, RR, CC, CC);
    bn_stats<<<16, 256>>>(pre, meanb, rstdb);
    lif_k<1><<<16, 256>>>(pre, nullptr, nullptr, meanb, rstdb,
                          gamma + 3 * 512, beta + 3 * 512, spk + TBC, LANES);

    // proj: GEMM + BN + LIF -> out
    sgemm_nt<<<gemm_grid, 256>>>(spk + TBC, wproj, pre, RR, CC, CC);
    bn_stats<<<16, 256>>>(pre, meanb, rstdb);
    lif_k<1><<<16, 256>>>(pre, nullptr, nullptr, meanb, rstdb,
                          gamma + 4 * 512, beta + 4 * 512, out, LANES);
}

// round 9
// speedup vs baseline: 1.2401x; 1.2401x over previous
#include <cuda_runtime.h>
#include <cuda_bf16.h>
#include <mma.h>
#include <math.h>
#include <stdint.h>

using namespace nvcuda;

#define TT   500
#define BB   8
#define CC   512
#define RR   4000
#define TBC  2048000
#define LANES 4096

// ---------------- scratch ----------------
__device__ float d_pre[3 * TBC];
__device__ float d_spk[3 * TBC];
__device__ float d_pre2[3 * TBC];
__device__ float d_spk2[3 * TBC];
__device__ float d_dwout[TBC];
__device__ float d_M[64 * 64 * 64];
__device__ float d_meanb[1536];
__device__ float d_rstdb[1536];
__device__ float d_bnpart[3 * 25 * 1024];
__device__ __nv_bfloat16 d_Aq[(size_t)4000 * 3072];
__device__ __nv_bfloat16 d_Bq[(size_t)1536 * 3072];
__device__ __nv_bfloat16 d_As[(size_t)4000 * 1536];
__device__ __nv_bfloat16 d_Bs0[(size_t)512 * 1536];
__device__ __nv_bfloat16 d_Bs1[(size_t)512 * 1536];

static __device__ __forceinline__ uint32_t smem_u32(const void* p) {
    return (uint32_t)__cvta_generic_to_shared(p);
}

// ---------------- bf16 3-way split ----------------
static __device__ __forceinline__ void split3(float x, __nv_bfloat16& a,
                                              __nv_bfloat16& b, __nv_bfloat16& c) {
    a = __float2bfloat16(x);
    float r = x - __bfloat162float(a);
    b = __float2bfloat16(r);
    r = r - __bfloat162float(b);
    c = __float2bfloat16(r);
}

// A' segs = [x1, x1, x2, x1, x2, x3]
__global__ void split_x_k(const float* __restrict__ x, __nv_bfloat16* __restrict__ A)
{
    int i = blockIdx.x * 256 + threadIdx.x;
    if (i >= TBC) return;
    __nv_bfloat16 a, b, c;
    split3(x[i], a, b, c);
    size_t base = (size_t)(i >> 9) * 3072 + (i & 511);
    A[base] = a; A[base + 512] = a; A[base + 1024] = b;
    A[base + 1536] = a; A[base + 2048] = b; A[base + 2560] = c;
}

// B' segs = [w1, w2, w1, w3, w2, w1]
__global__ void split_wqkv_k(const float* __restrict__ wq, const float* __restrict__ wk,
                             const float* __restrict__ wv, __nv_bfloat16* __restrict__ B)
{
    int i = blockIdx.x * 256 + threadIdx.x;
    if (i >= 1536 * 512) return;
    int n = i >> 9, k = i & 511;
    const float* w = (n < 512) ? wq : (n < 1024) ? wk : wv;
    __nv_bfloat16 a, b, c;
    split3(w[(size_t)(n & 511) * 512 + k], a, b, c);
    size_t base = (size_t)n * 3072 + k;
    B[base] = a; B[base + 512] = b; B[base + 1024] = a;
    B[base + 1536] = c; B[base + 2048] = b; B[base + 2560] = a;
}

// B'' segs = [w1, w2, w3]
__global__ void split_ws_k(const float* __restrict__ w, __nv_bfloat16* __restrict__ B)
{
    int i = blockIdx.x * 256 + threadIdx.x;
    if (i >= 512 * 512) return;
    int n = i >> 9, k = i & 511;
    __nv_bfloat16 a, b, c;
    split3(w[(size_t)n * 512 + k], a, b, c);
    size_t base = (size_t)n * 1536 + k;
    B[base] = a; B[base + 512] = b; B[base + 1024] = c;
}

// ---------------- cp.async helper ----------------
static __device__ __forceinline__ void cpa16(uint32_t dst, const void* src, bool ok)
{
    int sz = ok ? 16 : 0;
    asm volatile("cp.async.cg.shared.global [%0], [%1], 16, %2;"
                 :: "r"(dst), "l"(src), "r"(sz));
}

// ---------------- wmma bf16 GEMM (mma.sync / HMMA path) ----------------
// C[m,n] = sum_k A[m,k]*B[n,k]; A:[Mrows,Ktot], B:[N,Ktot] bf16 row-major.
// Output: outp[(n>>9)*segStride + m*512 + (n&511)], fp32.
// Tile 128x128, BK=32, 256 threads = 8 warps (4 x 2), warp tile 32x64.
#define LDT 40                 // smem row stride in elems (32 + 8 pad)
#define ABYTES 10240           // one A buffer: 128*40*2
__global__ __launch_bounds__(256)
void wmma_gemm(const __nv_bfloat16* __restrict__ A, const __nv_bfloat16* __restrict__ B,
               float* __restrict__ outp, int Mrows, int Ktot, size_t segStride)
{
    __shared__ __align__(16) __nv_bfloat16 sm[20480];  // A:2 bufs, B:2 bufs
    int tid = threadIdx.x, wid = tid >> 5, lane = tid & 31;
    int wr = wid >> 1, wc = wid & 1;
    uint32_t sa = smem_u32(sm);
    int bm = blockIdx.y * 128, bn = blockIdx.x * 128;
    const __nv_bfloat16* Ab = A + (size_t)bm * Ktot;
    const __nv_bfloat16* Bb = B + (size_t)bn * Ktot;
    int amax = Mrows - bm; if (amax > 128) amax = 128;

    // this thread's 2 chunks (16B each) of a 128x32 tile
    int ch0 = tid, ch1 = tid + 256;
    int r0 = ch0 >> 2, c0 = (ch0 & 3) * 8;
    int r1 = ch1 >> 2, c1 = (ch1 & 3) * 8;
    int r0c = (r0 < amax) ? r0 : (amax - 1);
    int r1c = (r1 < amax) ? r1 : (amax - 1);

    int nk = Ktot >> 5;

    // prologue: buffer 0
    cpa16(sa + (uint32_t)(r0 * LDT + c0) * 2, Ab + (size_t)r0c * Ktot + c0, r0 < amax);
    cpa16(sa + (uint32_t)(r1 * LDT + c1) * 2, Ab + (size_t)r1c * Ktot + c1, r1 < amax);
    cpa16(sa + 2 * ABYTES + (uint32_t)(r0 * LDT + c0) * 2, Bb + (size_t)r0 * Ktot + c0, true);
    cpa16(sa + 2 * ABYTES + (uint32_t)(r1 * LDT + c1) * 2, Bb + (size_t)r1 * Ktot + c1, true);
    asm volatile("cp.async.commit_group;");

    wmma::fragment<wmma::accumulator, 16, 16, 16, float> acc[2][4];
#pragma unroll
    for (int i = 0; i < 2; i++)
#pragma unroll
        for (int j = 0; j < 4; j++) wmma::fill_fragment(acc[i][j], 0.0f);

    for (int k0 = 0; k0 < nk; k0++) {
        if (k0 + 1 < nk) {
            int nb = (k0 + 1) & 1;
            int kof = (k0 + 1) * 32;
            uint32_t abo = sa + (uint32_t)nb * ABYTES;
            uint32_t bbo = sa + 2 * ABYTES + (uint32_t)nb * ABYTES;
            cpa16(abo + (uint32_t)(r0 * LDT + c0) * 2, Ab + (size_t)r0c * Ktot + kof + c0, r0 < amax);
            cpa16(abo + (uint32_t)(r1 * LDT + c1) * 2, Ab + (size_t)r1c * Ktot + kof + c1, r1 < amax);
            cpa16(bbo + (uint32_t)(r0 * LDT + c0) * 2, Bb + (size_t)r0 * Ktot + kof + c0, true);
            cpa16(bbo + (uint32_t)(r1 * LDT + c1) * 2, Bb + (size_t)r1 * Ktot + kof + c1, true);
            asm volatile("cp.async.commit_group;");
            asm volatile("cp.async.wait_group 1;");
        } else {
            asm volatile("cp.async.wait_group 0;");
        }
        __syncthreads();
        int buf = k0 & 1;
        const __nv_bfloat16* As_ = sm + buf * (ABYTES / 2);
        const __nv_bfloat16* Bs_ = sm + ABYTES + buf * (ABYTES / 2);
#pragma unroll
        for (int kk = 0; kk < 2; kk++) {
            wmma::fragment<wmma::matrix_a, 16, 16, 16, __nv_bfloat16, wmma::row_major> af[2];
            wmma::fragment<wmma::matrix_b, 16, 16, 16, __nv_bfloat16, wmma::col_major> bf[4];
#pragma unroll
            for (int i = 0; i < 2; i++)
                wmma::load_matrix_sync(af[i], As_ + (wr * 32 + i * 16) * LDT + kk * 16, LDT);
#pragma unroll
            for (int j = 0; j < 4; j++)
                wmma::load_matrix_sync(bf[j], Bs_ + (wc * 64 + j * 16) * LDT + kk * 16, LDT);
#pragma unroll
            for (int i = 0; i < 2; i++)
#pragma unroll
                for (int j = 0; j < 4; j++)
                    wmma::mma_sync(acc[i][j], af[i], bf[j], acc[i][j]);
        }
        __syncthreads();
    }

    float* outbase = outp + (size_t)(bn >> 9) * segStride + (bn & 511);
    if (amax == 128) {
#pragma unroll
        for (int i = 0; i < 2; i++)
#pragma unroll
            for (int j = 0; j < 4; j++) {
                int m = bm + wr * 32 + i * 16;
                int n = wc * 64 + j * 16;
                wmma::store_matrix_sync(outbase + (size_t)m * 512 + n, acc[i][j], 512,
                                        wmma::mem_row_major);
            }
    } else {
        __syncthreads();
        float* scr = (float*)sm + wid * 256;
#pragma unroll
        for (int i = 0; i < 2; i++)
#pragma unroll
            for (int j = 0; j < 4; j++) {
                wmma::store_matrix_sync(scr, acc[i][j], 16, wmma::mem_row_major);
                __syncwarp();
#pragma unroll
                for (int q = 0; q < 8; q++) {
                    int e = lane * 8 + q;
                    int r = e >> 4, cc = e & 15;
                    int m = bm + wr * 32 + i * 16 + r;
                    if (m < Mrows)
                        outbase[(size_t)m * 512 + wc * 64 + j * 16 + cc] = scr[e];
                }
                __syncwarp();
            }
    }
}

// ---------------- BN stats: deterministic 2-stage ----------------
__global__ void bn_part(const float* __restrict__ pre, float* __restrict__ part)
{
    int z = blockIdx.z;
    int cl = threadIdx.x & 31;
    int c = blockIdx.x * 32 + cl;
    int rg = threadIdx.x >> 5;
    const float* p = pre + (size_t)z * TBC;
    int r0 = blockIdx.y * 160;
    float s = 0.f, s2 = 0.f;
#pragma unroll 5
    for (int r = r0 + rg; r < r0 + 160; r += 8) {
        float v = p[(size_t)r * CC + c];
        s += v; s2 = fmaf(v, v, s2);
    }
    __shared__ float sh1[8][32], sh2[8][32];
    sh1[rg][cl] = s; sh2[rg][cl] = s2;
    __syncthreads();
    if (rg == 0) {
#pragma unroll
        for (int i = 1; i < 8; i++) { s += sh1[i][cl]; s2 += sh2[i][cl]; }
        size_t b = ((size_t)z * 25 + blockIdx.y) * 1024;
        part[b + c] = s;
        part[b + 512 + c] = s2;
    }
}

__global__ void bn_fin(const float* __restrict__ part, float* __restrict__ mean,
                       float* __restrict__ rstd)
{
    int z = blockIdx.x, c = threadIdx.x;
    float s = 0.f, s2 = 0.f;
#pragma unroll 5
    for (int i = 0; i < 25; i++) {
        size_t b = ((size_t)z * 25 + i) * 1024;
        s += part[b + c];
        s2 += part[b + 512 + c];
    }
    float m = s * (1.f / RR);
    float var = s2 * (1.f / RR) - m * m;
    mean[z * 512 + c] = m;
    rstd[z * 512 + c] = 1.f / sqrtf(var + 1e-5f);
}

// ---------------- LIF scan ----------------
// MODE 0: plain  MODE 1: BN affine  MODE 2: x = pre + a1 + a2
// WA: additionally emit bf16 triple [s,s,s] rows into abuf (K=1536 layout)
template <int MODE, int WA>
__global__ void lif_k(const float* __restrict__ pre,
                      const float* __restrict__ a1, const float* __restrict__ a2,
                      const float* __restrict__ mean, const float* __restrict__ rstd,
                      const float* __restrict__ gamma, const float* __restrict__ beta,
                      float* __restrict__ out, __nv_bfloat16* __restrict__ abuf,
                      int nlanes)
{
    int lane = blockIdx.x * blockDim.x + threadIdx.x;
    if (lane >= nlanes) return;
    int m   = lane >> 12;
    int l12 = lane & 4095;
    const float* p = pre + (size_t)m * TBC + l12;
    float* o = out + (size_t)m * TBC + l12;
    float mn = 0.f, rs = 1.f, ga = 1.f, be = 0.f;
    if (MODE == 1) {
        int c = (m << 9) | (l12 & 511);
        mn = mean[c]; rs = rstd[c]; ga = gamma[c]; be = beta[c];
    }
    int bidx = l12 >> 9, cch = l12 & 511;
    float v = 0.f;
#pragma unroll 10
    for (int t = 0; t < TT; t++) {
        float x = p[(size_t)t * LANES];
        if (MODE == 2) x = x + a1[l12 + (size_t)t * LANES] + a2[l12 + (size_t)t * LANES];
        if (MODE == 1) x = ((x - mn) * rs) * ga + be;
        float h = fmaf(v, 0.5f, x);
        bool sp = (h - 1.0f) >= 0.0f;
        o[(size_t)t * LANES] = sp ? 1.0f : 0.0f;
        if (WA) {
            __nv_bfloat16 sv = __float2bfloat16(sp ? 1.0f : 0.0f);
            size_t ab = ((size_t)(t * BB + bidx)) * 1536 + cch;
            abuf[ab] = sv; abuf[ab + 512] = sv; abuf[ab + 1024] = sv;
        }
        v = sp ? 0.0f : h;
    }
}

__global__ void zero_k(float* p, int n)
{
    int i = blockIdx.x * 256 + threadIdx.x;
    if (i < n) p[i] = 0.f;
}

// ---------------- K^T V per (b,h) ----------------
__global__ void kv_outer(const float* __restrict__ kspk, const float* __restrict__ vspk,
                         float* __restrict__ M)
{
    int bh = blockIdx.x; int b = bh >> 3, h = bh & 7;
    int t0 = blockIdx.y * 100;
    __shared__ float ks[20][64], vs[20][64];
    float acc[4][4] = {};
    int ty = (threadIdx.x >> 4) << 2, tx = (threadIdx.x & 15) << 2;
    for (int tb = t0; tb < t0 + 100; tb += 20) {
        __syncthreads();
        for (int i = threadIdx.x; i < 20 * 64; i += 256) {
            int tt = i >> 6, d = i & 63, t = tb + tt;
            size_t idx = (size_t)(t * BB + b) * CC + h * 64 + d;
            ks[tt][d] = kspk[idx]; vs[tt][d] = vspk[idx];
        }
        __syncthreads();
#pragma unroll
        for (int tt = 0; tt < 20; tt++) {
            float kr[4], vr[4];
#pragma unroll
            for (int i = 0; i < 4; i++) kr[i] = ks[tt][ty + i];
#pragma unroll
            for (int j = 0; j < 4; j++) vr[j] = vs[tt][tx + j];
#pragma unroll
            for (int i = 0; i < 4; i++)
#pragma unroll
                for (int j = 0; j < 4; j++) acc[i][j] = fmaf(kr[i], vr[j], acc[i][j]);
        }
    }
    float* Mb = M + bh * 4096;
#pragma unroll
    for (int i = 0; i < 4; i++)
#pragma unroll
        for (int j = 0; j < 4; j++) atomicAdd(&Mb[(ty + i) * 64 + tx + j], acc[i][j]);
}

// ---------------- global branch: g_pre = (Q M) * gscale ----------------
__global__ void qM_k(const float* __restrict__ qspk, const float* __restrict__ M,
                     float* __restrict__ gpre, float gscale)
{
    int bh = blockIdx.x; int b = bh >> 3, h = bh & 7;
    __shared__ float Ms[64][65];
    for (int i = threadIdx.x; i < 4096; i += 256) Ms[i >> 6][i & 63] = M[bh * 4096 + i];
    __syncthreads();
    int warp = threadIdx.x >> 5, lane = threadIdx.x & 31;
    int tstart = blockIdx.y * 100;
    for (int t = tstart + warp; t < tstart + 100; t += 8) {
        size_t base = (size_t)(t * BB + b) * CC + h * 64;
        float q0 = qspk[base + lane], q1 = qspk[base + 32 + lane];
        float a0 = 0.f, a1v = 0.f;
#pragma unroll
        for (int d1 = 0; d1 < 32; d1++) {
            float qv = __shfl_sync(0xffffffffu, q0, d1);
            a0 = fmaf(qv, Ms[d1][lane], a0);
            a1v = fmaf(qv, Ms[d1][lane + 32], a1v);
        }
#pragma unroll
        for (int d1 = 0; d1 < 32; d1++) {
            float qv = __shfl_sync(0xffffffffu, q1, d1);
            a0 = fmaf(qv, Ms[d1 + 32][lane], a0);
            a1v = fmaf(qv, Ms[d1 + 32][lane + 32], a1v);
        }
        gpre[base + lane] = a0 * gscale;
        gpre[base + 32 + lane] = a1v * gscale;
    }
}

// ---------------- local banded attention ----------------
__global__ void local_k(const float* __restrict__ qspk, const float* __restrict__ kspk,
                        const float* __restrict__ vspk, float* __restrict__ lpre, float lscale)
{
    int bh = blockIdx.x; int b = bh >> 3, h = bh & 7;
    int t0 = blockIdx.y * 64;
    __shared__ unsigned long long qb[64], kb[104];
    __shared__ float vsm[104][64];
    __shared__ float ss[64][41];
    int warp = threadIdx.x >> 5, lane = threadIdx.x & 31;
    for (int r = warp; r < 64; r += 8) {
        int t = t0 + r; float v0 = 0.f, v1 = 0.f;
        if (t < TT) { size_t idx = (size_t)(t * BB + b) * CC + h * 64; v0 = qspk[idx + lane]; v1 = qspk[idx + 32 + lane]; }
        unsigned m0 = __ballot_sync(0xffffffffu, v0 > 0.5f);
        unsigned m1 = __ballot_sync(0xffffffffu, v1 > 0.5f);
        if (lane == 0) qb[r] = (unsigned long long)m0 | ((unsigned long long)m1 << 32);
    }
    for (int r = warp; r < 104; r += 8) {
        int t = t0 + r - 20; float k0 = 0.f, k1 = 0.f, w0 = 0.f, w1 = 0.f;
        if (t >= 0 && t < TT) {
            size_t idx = (size_t)(t * BB + b) * CC + h * 64;
            k0 = kspk[idx + lane]; k1 = kspk[idx + 32 + lane];
            w0 = vspk[idx + lane]; w1 = vspk[idx + 32 + lane];
        }
        unsigned m0 = __ballot_sync(0xffffffffu, k0 > 0.5f);
        unsigned m1 = __ballot_sync(0xffffffffu, k1 > 0.5f);
        if (lane == 0) kb[r] = (unsigned long long)m0 | ((unsigned long long)m1 << 32);
        vsm[r][lane] = w0; vsm[r][lane + 32] = w1;
    }
    __syncthreads();
    for (int i = threadIdx.x; i < 64 * 41; i += 256) {
        int tt = i / 41, o = i % 41;
        ss[tt][o] = (float)__popcll(qb[tt] & kb[tt + o]);
    }
    __syncthreads();
    int d = threadIdx.x & 63, tg = threadIdx.x >> 6;
    for (int tt = tg; tt < 64; tt += 4) {
        int t = t0 + tt;
        if (t >= TT) continue;
        float acc = 0.f;
#pragma unroll
        for (int o = 0; o < 41; o++) acc = fmaf(ss[tt][o], vsm[tt + o][d], acc);
        lpre[(size_t)(t * BB + b) * CC + h * 64 + d] = acc * lscale;
    }
}

// ---------------- depthwise temporal conv ----------------
__global__ void dwconv_k(const float* __restrict__ vspk, const float* __restrict__ wdw,
                         float* __restrict__ out)
{
    int i = blockIdx.x * 256 + threadIdx.x;
    if (i >= TBC) return;
    int t = i >> 12; int bc = i & 4095; int c = bc & 511; int h = c >> 6;
    float acc = 0.f;
#pragma unroll
    for (int j = 0; j < 9; j++) {
        int tt = t + j - 4;
        if (tt >= 0 && tt < TT) acc = fmaf(vspk[(size_t)tt * LANES + bc], wdw[h * 9 + j], acc);
    }
    out[i] = acc;
}

// ---------------- pointwise over heads ----------------
__global__ void pw_k(const float* __restrict__ dwspk, const float* __restrict__ wpw,
                     float* __restrict__ out)
{
    int i = blockIdx.x * 256 + threadIdx.x;
    if (i >= 256000) return;
    int t = i / 512; int bd = i % 512; int b = bd >> 6; int d = bd & 63;
    size_t base = (size_t)t * LANES + b * 512 + d;
    float s[8];
#pragma unroll
    for (int h2 = 0; h2 < 8; h2++) s[h2] = dwspk[base + h2 * 64];
#pragma unroll
    for (int g = 0; g < 8; g++) {
        float acc = 0.f;
#pragma unroll
        for (int h2 = 0; h2 < 8; h2++) acc = fmaf(s[h2], wpw[g * 8 + h2], acc);
        out[base + g * 64] = acc;
    }
}

// ---------------- host launch ----------------
extern "C" void kernel_launch(void* const* d_in, const int* in_sizes, int n_in,
                              void* d_out, int out_size)
{
    const float* x      = (const float*)d_in[0];
    const float* wq     = (const float*)d_in[1];
    const float* wk     = (const float*)d_in[2];
    const float* wv     = (const float*)d_in[3];
    const float* wmattn = (const float*)d_in[4];
    const float* wproj  = (const float*)d_in[5];
    const float* wdw    = (const float*)d_in[6];
    const float* wpw    = (const float*)d_in[7];
    const float* gamma  = (const float*)d_in[8];
    const float* beta   = (const float*)d_in[9];
    float* out = (float*)d_out;

    float *pre, *spk, *pre2, *spk2, *dwout, *M, *meanb, *rstdb, *bnpart;
    __nv_bfloat16 *Aq, *Bq, *As, *Bs0, *Bs1;
    cudaGetSymbolAddress((void**)&pre,    d_pre);
    cudaGetSymbolAddress((void**)&spk,    d_spk);
    cudaGetSymbolAddress((void**)&pre2,   d_pre2);
    cudaGetSymbolAddress((void**)&spk2,   d_spk2);
    cudaGetSymbolAddress((void**)&dwout,  d_dwout);
    cudaGetSymbolAddress((void**)&M,      d_M);
    cudaGetSymbolAddress((void**)&meanb,  d_meanb);
    cudaGetSymbolAddress((void**)&rstdb,  d_rstdb);
    cudaGetSymbolAddress((void**)&bnpart, d_bnpart);
    cudaGetSymbolAddress((void**)&Aq,  d_Aq);
    cudaGetSymbolAddress((void**)&Bq,  d_Bq);
    cudaGetSymbolAddress((void**)&As,  d_As);
    cudaGetSymbolAddress((void**)&Bs0, d_Bs0);
    cudaGetSymbolAddress((void**)&Bs1, d_Bs1);

    float lscale = (float)(1.0 / (double)(float)sqrt(2624.0));
    float gscale = (float)(1.0 / (double)(float)sqrt(32000.0));

    // operand prep
    split_x_k<<<8000, 256>>>(x, Aq);
    split_wqkv_k<<<3072, 256>>>(wq, wk, wv, Bq);
    split_ws_k<<<1024, 256>>>(wmattn, Bs0);
    split_ws_k<<<1024, 256>>>(wproj, Bs1);

    // QKV: one wmma GEMM, N=1536 -> q,k,v pre-activations
    wmma_gemm<<<dim3(12, 32), 256>>>(Aq, Bq, pre, RR, 3072, (size_t)TBC);
    bn_part<<<dim3(16, 25, 3), 256>>>(pre, bnpart);
    bn_fin<<<3, 512>>>(bnpart, meanb, rstdb);
    lif_k<1, 0><<<48, 256>>>(pre, nullptr, nullptr, meanb, rstdb, gamma, beta,
                             spk, nullptr, 3 * LANES);

    // global linear attention
    zero_k<<<1024, 256>>>(M, 64 * 4096);
    kv_outer<<<dim3(64, 5), 256>>>(spk + TBC, spk + 2 * TBC, M);
    qM_k<<<dim3(64, 5), 256>>>(spk, M, pre2, gscale);

    // local banded attention
    local_k<<<dim3(64, 8), 256>>>(spk, spk + TBC, spk + 2 * TBC, pre2 + TBC, lscale);

    // depthwise temporal conv on V
    dwconv_k<<<8000, 256>>>(spk + 2 * TBC, wdw, pre2 + 2 * TBC);

    // LIF over [g_pre, l_pre, dw_pre]
    lif_k<0, 0><<<48, 256>>>(pre2, nullptr, nullptr, nullptr, nullptr, nullptr, nullptr,
                             spk2, nullptr, 3 * LANES);

    // pointwise over heads on dw spikes
    pw_k<<<1000, 256>>>(spk2 + 2 * TBC, wpw, dwout);

    // y0 = LIF(g + l + dw), also emit bf16 A'' for mattn GEMM
    lif_k<2, 1><<<16, 256>>>(spk2, spk2 + TBC, dwout, nullptr, nullptr, nullptr, nullptr,
                             spk, As, LANES);

    // mattn GEMM + BN + LIF -> y1 (emits A'' for proj GEMM)
    wmma_gemm<<<dim3(4, 32), 256>>>(As, Bs0, pre, RR, 1536, (size_t)TBC);
    bn_part<<<dim3(16, 25, 1), 256>>>(pre, bnpart);
    bn_fin<<<1, 512>>>(bnpart, meanb, rstdb);
    lif_k<1, 1><<<16, 256>>>(pre, nullptr, nullptr, meanb, rstdb,
                             gamma + 3 * 512, beta + 3 * 512, spk + TBC, As, LANES);

    // proj GEMM + BN + LIF -> out
    wmma_gemm<<<dim3(4, 32), 256>>>(As, Bs1, pre, RR, 1536, (size_t)TBC);
    bn_part<<<dim3(16, 25, 1), 256>>>(pre, bnpart);
    bn_fin<<<1, 512>>>(bnpart, meanb, rstdb);
    lif_k<1, 0><<<16, 256>>>(pre, nullptr, nullptr, meanb, rstdb,
                             gamma + 4 * 512, beta + 4 * 512, out, nullptr, LANES);
}